// round 2
// baseline (speedup 1.0000x reference)
#include <cuda_runtime.h>
#include <cuda_bf16.h>
#include <cstddef>

#define N_NODES 50000
#define E_EDGES 800000
#define IN_DIM  128
#define H_DIM   96
#define PN_SCALE 20.0f
#define BN_EPS   1e-5f

// ---------------- scratch (static device globals; no allocation) ----------------
__device__ float g_z[(size_t)N_NODES * H_DIM];      // z = h0 + agg
__device__ float g_h[(size_t)N_NODES * H_DIM];      // h = z@W1^T + b1 (pre-BN)
__device__ float g_stats[3 * H_DIM];                // [0:96) bn sum, [96:192) bn sumsq, [192:288) l1 col sum
__device__ float g_bnscale[H_DIM];
__device__ float g_bnshift[H_DIM];

// ---------------- tiny kernels ----------------
__global__ void zero_stats_kernel() {
    int i = threadIdx.x;
    if (i < 3 * H_DIM) g_stats[i] = 0.0f;
}

__global__ void bn_finalize_kernel(const float* __restrict__ gamma,
                                   const float* __restrict__ beta) {
    int c = threadIdx.x;
    if (c >= H_DIM) return;
    const float invN = 1.0f / (float)N_NODES;
    float mean = g_stats[c] * invN;
    float var  = g_stats[H_DIM + c] * invN - mean * mean;
    float scale = gamma[c] * rsqrtf(var + BN_EPS);
    g_bnscale[c] = scale;
    g_bnshift[c] = beta[c] - mean * scale;
}

// ---------------- tiled SGEMM: out[M,96] = A[M,KD] @ W[96,KD]^T + bias ----------------
// AMODE: 0 = A param, 1 = g_z, 2 = g_h
// DMODE: 0 = out param, 1 = out param AND g_z (dual store), 2 = g_h
// TRANS: apply per-k BN affine + ReLU to A elements on load
template<int KD, int AMODE, int DMODE, bool TRANS>
__global__ __launch_bounds__(256) void gemm_kernel(
    const float* __restrict__ A, const float* __restrict__ W,
    const float* __restrict__ bias, float* __restrict__ outp, int M)
{
    constexpr int BM = 128;
    constexpr int BK = 16;
    __shared__ float As[BK][BM];        // [k][m]
    __shared__ float Bs[BK][H_DIM];     // [k][n]
    __shared__ float s_scale[H_DIM];
    __shared__ float s_shift[H_DIM];

    const float* Aptr = (AMODE == 0) ? A : ((AMODE == 1) ? g_z : g_h);

    const int tid = threadIdx.x;
    const int tx = tid & 15;    // col group: cols [tx*6, tx*6+6)
    const int ty = tid >> 4;    // row group: rows [ty*8, ty*8+8)
    const int row0 = blockIdx.x * BM;

    if (TRANS) {
        if (tid < H_DIM) { s_scale[tid] = g_bnscale[tid]; s_shift[tid] = g_bnshift[tid]; }
    }
    __syncthreads();

    float acc[8][6];
    #pragma unroll
    for (int i = 0; i < 8; i++)
        #pragma unroll
        for (int j = 0; j < 6; j++) acc[i][j] = 0.0f;

    for (int k0 = 0; k0 < KD; k0 += BK) {
        // load A tile (128 rows x 16 k) as float4s; 512 float4s / 256 threads = 2 each
        #pragma unroll
        for (int i = 0; i < 2; i++) {
            int idx = tid + i * 256;
            int r = idx >> 2;
            int kq = (idx & 3) << 2;
            int grow = row0 + r;
            float4 v = make_float4(0.f, 0.f, 0.f, 0.f);
            if (grow < M) {
                v = *(const float4*)(Aptr + (size_t)grow * KD + k0 + kq);
                if (TRANS) {
                    v.x = fmaxf(0.f, fmaf(v.x, s_scale[k0 + kq + 0], s_shift[k0 + kq + 0]));
                    v.y = fmaxf(0.f, fmaf(v.y, s_scale[k0 + kq + 1], s_shift[k0 + kq + 1]));
                    v.z = fmaxf(0.f, fmaf(v.z, s_scale[k0 + kq + 2], s_shift[k0 + kq + 2]));
                    v.w = fmaxf(0.f, fmaf(v.w, s_scale[k0 + kq + 3], s_shift[k0 + kq + 3]));
                }
            }
            As[kq + 0][r] = v.x;
            As[kq + 1][r] = v.y;
            As[kq + 2][r] = v.z;
            As[kq + 3][r] = v.w;
        }
        // load W tile (96 n x 16 k): 1536 floats / 256 threads = 6 each
        #pragma unroll
        for (int i = tid; i < H_DIM * BK; i += 256) {
            int n = i >> 4;
            int k = i & 15;
            Bs[k][n] = W[(size_t)n * KD + k0 + k];
        }
        __syncthreads();

        #pragma unroll
        for (int k = 0; k < BK; k++) {
            float4 a0 = *(const float4*)&As[k][ty * 8];
            float4 a1 = *(const float4*)&As[k][ty * 8 + 4];
            float ar[8] = {a0.x, a0.y, a0.z, a0.w, a1.x, a1.y, a1.z, a1.w};
            float br[6];
            #pragma unroll
            for (int j = 0; j < 6; j++) br[j] = Bs[k][tx * 6 + j];
            #pragma unroll
            for (int i = 0; i < 8; i++)
                #pragma unroll
                for (int j = 0; j < 6; j++)
                    acc[i][j] = fmaf(ar[i], br[j], acc[i][j]);
        }
        __syncthreads();
    }

    // epilogue
    #pragma unroll
    for (int i = 0; i < 8; i++) {
        int grow = row0 + ty * 8 + i;
        if (grow < M) {
            #pragma unroll
            for (int j = 0; j < 6; j++) {
                int col = tx * 6 + j;
                float val = acc[i][j] + bias[col];
                size_t ofs = (size_t)grow * H_DIM + col;
                if (DMODE == 2) g_h[ofs] = val;
                else            outp[ofs] = val;
                if (DMODE == 1) g_z[ofs] = val;
            }
        }
    }
}

// ---------------- edge scatter: g_z[dst] += h0[src] ----------------
// 24 float4 chunks per edge; one thread per (edge, chunk)
__global__ __launch_bounds__(256) void scatter_kernel(const int* __restrict__ ei,
                                                      const float* __restrict__ h0) {
    int g = blockIdx.x * 256 + threadIdx.x;      // < E*24 = 19.2M, fits int
    int e = g / 24;
    int c = (g - e * 24) << 2;                   // feature offset (0,4,...,92)
    int s = __ldg(ei + e);
    int d = __ldg(ei + E_EDGES + e);
    const float4 v = *(const float4*)(h0 + (size_t)s * H_DIM + c);
    float* p = g_z + (size_t)d * H_DIM + c;
    atomicAdd(p + 0, v.x);
    atomicAdd(p + 1, v.y);
    atomicAdd(p + 2, v.z);
    atomicAdd(p + 3, v.w);
}

// ---------------- per-column stats ----------------
// SRC: 0 = param X (l1 pre-pairnorm), 1 = g_h.  SQ: also accumulate sum of squares.
// SQ=true writes g_stats[0..191]; SQ=false writes g_stats[192..287].
template<int SRC, bool SQ>
__global__ void colstats_kernel(const float* __restrict__ X) {
    __shared__ float ssum[4][H_DIM];
    __shared__ float ssq[4][H_DIM];
    const float* Xp = (SRC == 0) ? X : g_h;
    int c = threadIdx.x;       // 0..95
    int y = threadIdx.y;       // 0..3
    int r0 = blockIdx.x * 256;
    float s = 0.f, q = 0.f;
    for (int r = r0 + y; r < N_NODES && r < r0 + 256; r += 4) {
        float v = Xp[(size_t)r * H_DIM + c];
        s += v;
        if (SQ) q += v * v;
    }
    ssum[y][c] = s;
    if (SQ) ssq[y][c] = q;
    __syncthreads();
    if (y == 0) {
        s = ssum[0][c] + ssum[1][c] + ssum[2][c] + ssum[3][c];
        if (SQ) {
            q = ssq[0][c] + ssq[1][c] + ssq[2][c] + ssq[3][c];
            atomicAdd(&g_stats[c], s);
            atomicAdd(&g_stats[H_DIM + c], q);
        } else {
            atomicAdd(&g_stats[2 * H_DIM + c], s);
        }
    }
}

// ---------------- PairNorm (in place on d_out l1 region) ----------------
__global__ __launch_bounds__(256) void pairnorm_kernel(float* __restrict__ out) {
    int row = blockIdx.x * 8 + (threadIdx.x >> 5);
    if (row >= N_NODES) return;
    int lane = threadIdx.x & 31;
    float* r = out + (size_t)row * H_DIM;
    float v0 = r[lane], v1 = r[lane + 32], v2 = r[lane + 64];
    float ss = v0 * v0 + v1 * v1 + v2 * v2;
    #pragma unroll
    for (int o = 16; o; o >>= 1) ss += __shfl_xor_sync(0xffffffffu, ss, o);
    float sc = PN_SCALE * rsqrtf(1e-6f + ss);
    const float invN = 1.0f / (float)N_NODES;
    r[lane]      = v0 * sc - g_stats[2 * H_DIM + lane]      * invN;
    r[lane + 32] = v1 * sc - g_stats[2 * H_DIM + lane + 32] * invN;
    r[lane + 64] = v2 * sc - g_stats[2 * H_DIM + lane + 64] * invN;
}

// ---------------- launch ----------------
extern "C" void kernel_launch(void* const* d_in, const int* in_sizes, int n_in,
                              void* d_out, int out_size) {
    const float* x     = (const float*)d_in[0];
    const int*   ei    = (const int*)  d_in[1];
    const float* W0    = (const float*)d_in[2];
    const float* b0    = (const float*)d_in[3];
    const float* W1    = (const float*)d_in[4];
    const float* b1    = (const float*)d_in[5];
    const float* gamma = (const float*)d_in[6];
    const float* beta  = (const float*)d_in[7];
    const float* W2    = (const float*)d_in[8];
    const float* b2    = (const float*)d_in[9];

    float* l1 = (float*)d_out;                          // [N, H]
    float* h0 = (float*)d_out + (size_t)N_NODES * H_DIM; // [N, H]

    const int gemm_blocks = (N_NODES + 127) / 128;       // 391
    const int stats_blocks = (N_NODES + 255) / 256;      // 196

    zero_stats_kernel<<<1, 3 * H_DIM>>>();

    // h0 = x @ W0^T + b0 ; also init g_z = h0
    gemm_kernel<IN_DIM, 0, 1, false><<<gemm_blocks, 256>>>(x, W0, b0, h0, N_NODES);

    // g_z[dst] += h0[src] for all edges
    scatter_kernel<<<(E_EDGES * 24) / 256, 256>>>(ei, h0);

    // g_h = g_z @ W1^T + b1
    gemm_kernel<H_DIM, 1, 2, false><<<gemm_blocks, 256>>>(nullptr, W1, b1, nullptr, N_NODES);

    // BN stats over g_h
    colstats_kernel<1, true><<<stats_blocks, dim3(H_DIM, 4)>>>(nullptr);
    bn_finalize_kernel<<<1, H_DIM>>>(gamma, beta);

    // l1 = relu(bn(g_h)) @ W2^T + b2   (BN+ReLU fused into A-tile load)
    gemm_kernel<H_DIM, 2, 0, true><<<gemm_blocks, 256>>>(nullptr, W2, b2, l1, N_NODES);

    // column sums of l1 for PairNorm
    colstats_kernel<0, false><<<stats_blocks, dim3(H_DIM, 4)>>>(l1);

    // PairNorm in place
    pairnorm_kernel<<<(N_NODES + 7) / 8, 256>>>(l1);
}

// round 6
// speedup vs baseline: 1.5311x; 1.5311x over previous
#include <cuda_runtime.h>
#include <cuda_bf16.h>
#include <cstddef>

#define N_NODES 50000
#define E_EDGES 800000
#define IN_DIM  128
#define H_DIM   96
#define PN_SCALE 20.0f
#define BN_EPS   1e-5f

// ---------------- scratch (static device globals; no allocation) ----------------
__device__ float g_z[(size_t)N_NODES * H_DIM];      // z = h0 + agg
__device__ float g_h[(size_t)N_NODES * H_DIM];      // h = z@W1^T + b1 (pre-BN)
__device__ float g_stats[3 * H_DIM];                // [0:96) bn sum, [96:192) bn sumsq, [192:288) l1 col sum
__device__ float g_bnscale[H_DIM];
__device__ float g_bnshift[H_DIM];

// ---------------- tiny kernels ----------------
__global__ void zero_stats_kernel() {
    int i = threadIdx.x;
    if (i < 3 * H_DIM) g_stats[i] = 0.0f;
}

__global__ void bn_finalize_kernel(const float* __restrict__ gamma,
                                   const float* __restrict__ beta) {
    int c = threadIdx.x;
    if (c >= H_DIM) return;
    const float invN = 1.0f / (float)N_NODES;
    float mean = g_stats[c] * invN;
    float var  = g_stats[H_DIM + c] * invN - mean * mean;
    float scale = gamma[c] * rsqrtf(var + BN_EPS);
    g_bnscale[c] = scale;
    g_bnshift[c] = beta[c] - mean * scale;
}

// ---------------- double-buffered SGEMM: out[M,96] = A[M,KD] @ W[96,KD]^T + bias --------
// AMODE: 0 = A param, 1 = g_z, 2 = g_h
// DMODE: 0 = out param, 1 = out param AND g_z (dual store), 2 = g_h
// TRANS: apply per-k BN affine + ReLU to A elements when storing to smem
// STATS: 0 none, 1 accumulate BN sum+sumsq of outputs, 2 accumulate col-sum of outputs
template<int KD, int AMODE, int DMODE, bool TRANS, int STATS>
__global__ __launch_bounds__(256, 2) void gemm_kernel(
    const float* __restrict__ A, const float* __restrict__ W,
    const float* __restrict__ bias, float* __restrict__ outp, int M)
{
    constexpr int BM = 128;
    constexpr int BK = 16;
    __shared__ float As[2][BK][BM];
    __shared__ float Bs[2][BK][H_DIM];
    __shared__ float s_scale[TRANS ? H_DIM : 1];
    __shared__ float s_shift[TRANS ? H_DIM : 1];
    __shared__ float sred [STATS ? 16 : 1][H_DIM];
    __shared__ float sred2[STATS == 1 ? 16 : 1][H_DIM];

    const float* Aptr = (AMODE == 0) ? A : ((AMODE == 1) ? g_z : g_h);

    const int tid = threadIdx.x;
    const int tx = tid & 15;    // col group: cols [tx*6, tx*6+6)
    const int ty = tid >> 4;    // row group: rows [ty*8, ty*8+8)
    const int row0 = blockIdx.x * BM;

    // A-tile load coordinates for this thread (2 float4s per tile)
    const int r_a0  = tid >> 2;
    const int kq_a0 = (tid & 3) << 2;
    const int r_a1  = (tid + 256) >> 2;
    const int kq_a1 = ((tid + 256) & 3) << 2;

    if (TRANS) {
        if (tid < H_DIM) { s_scale[tid] = g_bnscale[tid]; s_shift[tid] = g_bnshift[tid]; }
        __syncthreads();
    }

    float acc[8][6];
    #pragma unroll
    for (int i = 0; i < 8; i++)
        #pragma unroll
        for (int j = 0; j < 6; j++) acc[i][j] = 0.0f;

    auto load_a = [&](int k0, int r, int kq) -> float4 {
        int grow = row0 + r;
        float4 v = make_float4(0.f, 0.f, 0.f, 0.f);
        if (grow < M) v = *(const float4*)(Aptr + (size_t)grow * KD + k0 + kq);
        return v;
    };
    auto trans_a = [&](float4 v, int kk) -> float4 {
        if (TRANS) {
            v.x = fmaxf(0.f, fmaf(v.x, s_scale[kk + 0], s_shift[kk + 0]));
            v.y = fmaxf(0.f, fmaf(v.y, s_scale[kk + 1], s_shift[kk + 1]));
            v.z = fmaxf(0.f, fmaf(v.z, s_scale[kk + 2], s_shift[kk + 2]));
            v.w = fmaxf(0.f, fmaf(v.w, s_scale[kk + 3], s_shift[kk + 3]));
        }
        return v;
    };
    auto store_a = [&](int buf, int r, int kq, float4 v) {
        As[buf][kq + 0][r] = v.x;
        As[buf][kq + 1][r] = v.y;
        As[buf][kq + 2][r] = v.z;
        As[buf][kq + 3][r] = v.w;
    };
    auto compute = [&](int buf) {
        #pragma unroll
        for (int k = 0; k < BK; k++) {
            float4 a0 = *(const float4*)&As[buf][k][ty * 8];
            float4 a1 = *(const float4*)&As[buf][k][ty * 8 + 4];
            float2 b0 = *(const float2*)&Bs[buf][k][tx * 6];
            float2 b1 = *(const float2*)&Bs[buf][k][tx * 6 + 2];
            float2 b2 = *(const float2*)&Bs[buf][k][tx * 6 + 4];
            float ar[8] = {a0.x, a0.y, a0.z, a0.w, a1.x, a1.y, a1.z, a1.w};
            float br[6] = {b0.x, b0.y, b1.x, b1.y, b2.x, b2.y};
            #pragma unroll
            for (int i = 0; i < 8; i++)
                #pragma unroll
                for (int j = 0; j < 6; j++)
                    acc[i][j] = fmaf(ar[i], br[j], acc[i][j]);
        }
    };

    // ---- prologue: fill buffer 0 ----
    store_a(0, r_a0, kq_a0, trans_a(load_a(0, r_a0, kq_a0), kq_a0));
    store_a(0, r_a1, kq_a1, trans_a(load_a(0, r_a1, kq_a1), kq_a1));
    #pragma unroll
    for (int i = 0; i < 6; i++) {
        int id = tid + i * 256;
        int n = id >> 4, k = id & 15;
        Bs[0][k][n] = W[(size_t)n * KD + k];
    }
    __syncthreads();

    // ---- steady state: prefetch next, compute current, store next, sync ----
    int cur = 0;
    for (int k0 = BK; k0 < KD; k0 += BK) {
        float4 pa0 = load_a(k0, r_a0, kq_a0);
        float4 pa1 = load_a(k0, r_a1, kq_a1);
        float pb[6];
        #pragma unroll
        for (int i = 0; i < 6; i++) {
            int id = tid + i * 256;
            int n = id >> 4, k = id & 15;
            pb[i] = W[(size_t)n * KD + k0 + k];
        }

        compute(cur);

        store_a(cur ^ 1, r_a0, kq_a0, trans_a(pa0, k0 + kq_a0));
        store_a(cur ^ 1, r_a1, kq_a1, trans_a(pa1, k0 + kq_a1));
        #pragma unroll
        for (int i = 0; i < 6; i++) {
            int id = tid + i * 256;
            int n = id >> 4, k = id & 15;
            Bs[cur ^ 1][k][n] = pb[i];
        }
        __syncthreads();
        cur ^= 1;
    }
    compute(cur);

    // ---- epilogue: bias, store, optional fused column reductions ----
    float csum[6] = {0, 0, 0, 0, 0, 0};
    float csq [6] = {0, 0, 0, 0, 0, 0};
    #pragma unroll
    for (int i = 0; i < 8; i++) {
        int grow = row0 + ty * 8 + i;
        if (grow < M) {
            #pragma unroll
            for (int j = 0; j < 6; j++) {
                int col = tx * 6 + j;
                float val = acc[i][j] + bias[col];
                size_t ofs = (size_t)grow * H_DIM + col;
                if (DMODE == 2) g_h[ofs] = val;
                else            outp[ofs] = val;
                if (DMODE == 1) g_z[ofs] = val;
                if (STATS) {
                    csum[j] += val;
                    if (STATS == 1) csq[j] += val * val;
                }
            }
        }
    }
    if (STATS) {
        #pragma unroll
        for (int j = 0; j < 6; j++) {
            sred[ty][tx * 6 + j] = csum[j];
            if (STATS == 1) sred2[ty][tx * 6 + j] = csq[j];
        }
        __syncthreads();
        if (ty == 0) {
            #pragma unroll
            for (int j = 0; j < 6; j++) {
                int col = tx * 6 + j;
                float s = 0.f, q = 0.f;
                #pragma unroll
                for (int t = 0; t < 16; t++) {
                    s += sred[t][col];
                    if (STATS == 1) q += sred2[t][col];
                }
                if (STATS == 1) {
                    atomicAdd(&g_stats[col], s);
                    atomicAdd(&g_stats[H_DIM + col], q);
                } else {
                    atomicAdd(&g_stats[2 * H_DIM + col], s);
                }
            }
        }
    }
}

// ---------------- edge scatter: g_z[dst] += h0[src], vectorized red.v4 ----------------
__global__ __launch_bounds__(256) void scatter_kernel(const int* __restrict__ ei,
                                                      const float* __restrict__ h0) {
    int g = blockIdx.x * 256 + threadIdx.x;      // < E*24 = 19.2M
    int e = g / 24;
    int c = (g - e * 24) << 2;                   // feature offset (0,4,...,92)
    int s = __ldg(ei + e);
    int d = __ldg(ei + E_EDGES + e);
    const float4 v = *(const float4*)(h0 + (size_t)s * H_DIM + c);
    float* p = g_z + (size_t)d * H_DIM + c;
    asm volatile("red.global.add.v4.f32 [%0], {%1, %2, %3, %4};"
                 :: "l"(p), "f"(v.x), "f"(v.y), "f"(v.z), "f"(v.w) : "memory");
}

// ---------------- PairNorm (in place on d_out l1 region) ----------------
__global__ __launch_bounds__(256) void pairnorm_kernel(float* __restrict__ out) {
    int row = blockIdx.x * 8 + (threadIdx.x >> 5);
    if (row >= N_NODES) return;
    int lane = threadIdx.x & 31;
    float* r = out + (size_t)row * H_DIM;
    float v0 = r[lane], v1 = r[lane + 32], v2 = r[lane + 64];
    float ss = v0 * v0 + v1 * v1 + v2 * v2;
    #pragma unroll
    for (int o = 16; o; o >>= 1) ss += __shfl_xor_sync(0xffffffffu, ss, o);
    float sc = PN_SCALE * rsqrtf(1e-6f + ss);
    const float invN = 1.0f / (float)N_NODES;
    r[lane]      = v0 * sc - g_stats[2 * H_DIM + lane]      * invN;
    r[lane + 32] = v1 * sc - g_stats[2 * H_DIM + lane + 32] * invN;
    r[lane + 64] = v2 * sc - g_stats[2 * H_DIM + lane + 64] * invN;
}

// ---------------- launch ----------------
extern "C" void kernel_launch(void* const* d_in, const int* in_sizes, int n_in,
                              void* d_out, int out_size) {
    const float* x     = (const float*)d_in[0];
    const int*   ei    = (const int*)  d_in[1];
    const float* W0    = (const float*)d_in[2];
    const float* b0    = (const float*)d_in[3];
    const float* W1    = (const float*)d_in[4];
    const float* b1    = (const float*)d_in[5];
    const float* gamma = (const float*)d_in[6];
    const float* beta  = (const float*)d_in[7];
    const float* W2    = (const float*)d_in[8];
    const float* b2    = (const float*)d_in[9];

    float* l1 = (float*)d_out;                           // [N, H]
    float* h0 = (float*)d_out + (size_t)N_NODES * H_DIM; // [N, H]

    const int gemm_blocks = (N_NODES + 127) / 128;       // 391

    zero_stats_kernel<<<1, 3 * H_DIM>>>();

    // h0 = x @ W0^T + b0 ; also init g_z = h0
    gemm_kernel<IN_DIM, 0, 1, false, 0><<<gemm_blocks, 256>>>(x, W0, b0, h0, N_NODES);

    // g_z[dst] += h0[src] for all edges (vectorized red)
    scatter_kernel<<<(E_EDGES * 24) / 256, 256>>>(ei, h0);

    // g_h = g_z @ W1^T + b1 ; fused BN sum/sumsq
    gemm_kernel<H_DIM, 1, 2, false, 1><<<gemm_blocks, 256>>>(nullptr, W1, b1, nullptr, N_NODES);

    bn_finalize_kernel<<<1, H_DIM>>>(gamma, beta);

    // l1 = relu(bn(g_h)) @ W2^T + b2 ; fused PairNorm col-sum
    gemm_kernel<H_DIM, 2, 0, true, 2><<<gemm_blocks, 256>>>(nullptr, W2, b2, l1, N_NODES);

    // PairNorm in place
    pairnorm_kernel<<<(N_NODES + 7) / 8, 256>>>(l1);
}

// round 7
// speedup vs baseline: 1.8349x; 1.1984x over previous
#include <cuda_runtime.h>
#include <cuda_bf16.h>
#include <cstdint>
#include <cstddef>

#define N_NODES 50000
#define E_EDGES 800000
#define IN_DIM  128
#define H_DIM   96
#define PN_SCALE 20.0f
#define BN_EPS   1e-5f

// ---------------- scratch (static device globals; no allocation) ----------------
__device__ float g_z[(size_t)N_NODES * H_DIM];      // z = h0 + agg
__device__ float g_h[(size_t)N_NODES * H_DIM];      // h = z@W1^T + b1 (pre-BN)
__device__ float g_stats[3 * H_DIM];                // [0:96) bn sum, [96:192) bn sumsq, [192:288) l1 col sum
__device__ float g_bnscale[H_DIM];
__device__ float g_bnshift[H_DIM];

// ---------------- helpers ----------------
__device__ __forceinline__ float to_tf32(float x) {
    uint32_t u;
    asm("cvt.rna.tf32.f32 %0, %1;" : "=r"(u) : "f"(x));
    return __uint_as_float(u);
}

__device__ __forceinline__ void mma_tf32(float c[4], const uint32_t a[4], const uint32_t b[2]) {
    asm volatile(
        "mma.sync.aligned.m16n8k8.row.col.f32.tf32.tf32.f32 "
        "{%0,%1,%2,%3},{%4,%5,%6,%7},{%8,%9},{%0,%1,%2,%3};"
        : "+f"(c[0]), "+f"(c[1]), "+f"(c[2]), "+f"(c[3])
        : "r"(a[0]), "r"(a[1]), "r"(a[2]), "r"(a[3]), "r"(b[0]), "r"(b[1]));
}

// ---------------- tiny kernels ----------------
__global__ void zero_stats_kernel() {
    int i = threadIdx.x;
    if (i < 3 * H_DIM) g_stats[i] = 0.0f;
}

__global__ void bn_finalize_kernel(const float* __restrict__ gamma,
                                   const float* __restrict__ beta) {
    int c = threadIdx.x;
    if (c >= H_DIM) return;
    const float invN = 1.0f / (float)N_NODES;
    float mean = g_stats[c] * invN;
    float var  = g_stats[H_DIM + c] * invN - mean * mean;
    float scale = gamma[c] * rsqrtf(var + BN_EPS);
    g_bnscale[c] = scale;
    g_bnshift[c] = beta[c] - mean * scale;
}

// ---------------- tf32 tensor-core GEMM: out[M,96] = A[M,KD] @ W[96,KD]^T + bias ------
// AMODE: 0 = A param, 1 = g_z, 2 = g_h
// DMODE: 0 = out param, 1 = out param AND g_z (dual store), 2 = g_h
// TRANS: apply per-k BN affine + ReLU to A elements when storing to smem
// STATS: 0 none, 1 accumulate BN sum+sumsq of outputs, 2 accumulate col-sum of outputs
//
// Block: 256 thr = 8 warps, 4(M) x 2(N). Tile BM=128 x 96. Warp tile 32x48.
// Smem k-major, padded so fragment LDS.32 reads are bank-conflict-free:
//   As stride 136 -> bank = (q*8+g) all distinct;  Bs stride 104 -> same.
template<int KD, int AMODE, int DMODE, bool TRANS, int STATS>
__global__ __launch_bounds__(256, 2) void gemm_kernel(
    const float* __restrict__ A, const float* __restrict__ W,
    const float* __restrict__ bias, float* __restrict__ outp, int M)
{
    constexpr int BM = 128;
    constexpr int BK = 16;
    constexpr int PAD_M = 136;
    constexpr int PAD_N = 104;
    __shared__ float As[2][BK][PAD_M];
    __shared__ float Bs[2][BK][PAD_N];
    __shared__ float s_scale[TRANS ? H_DIM : 1];
    __shared__ float s_shift[TRANS ? H_DIM : 1];

    const float* Aptr = (AMODE == 0) ? A : ((AMODE == 1) ? g_z : g_h);

    const int tid = threadIdx.x;
    const int lane = tid & 31;
    const int wid = tid >> 5;
    const int warp_m = wid & 3;        // 0..3 -> rows [warp_m*32, +32)
    const int warp_n = wid >> 2;       // 0..1 -> cols [warp_n*48, +48)
    const int g = lane >> 2;           // 0..7
    const int q = lane & 3;            // 0..3
    const int row0 = blockIdx.x * BM;

    // A-tile loader coordinates (2 float4 per thread per BK=16 tile)
    const int r_a0  = tid >> 2;
    const int kq_a0 = (tid & 3) << 2;
    const int r_a1  = (tid + 256) >> 2;
    const int kq_a1 = ((tid + 256) & 3) << 2;

    if (TRANS) {
        if (tid < H_DIM) { s_scale[tid] = g_bnscale[tid]; s_shift[tid] = g_bnshift[tid]; }
        __syncthreads();
    }

    float acc[2][6][4];
    #pragma unroll
    for (int mt = 0; mt < 2; mt++)
        #pragma unroll
        for (int nt = 0; nt < 6; nt++)
            #pragma unroll
            for (int j = 0; j < 4; j++) acc[mt][nt][j] = 0.0f;

    auto load_a = [&](int k0, int r, int kq) -> float4 {
        int grow = row0 + r;
        float4 v = make_float4(0.f, 0.f, 0.f, 0.f);
        if (grow < M) v = *(const float4*)(Aptr + (size_t)grow * KD + k0 + kq);
        return v;
    };
    auto store_a = [&](int buf, int r, int kq, float4 v, int kk) {
        if (TRANS) {
            v.x = fmaxf(0.f, fmaf(v.x, s_scale[kk + 0], s_shift[kk + 0]));
            v.y = fmaxf(0.f, fmaf(v.y, s_scale[kk + 1], s_shift[kk + 1]));
            v.z = fmaxf(0.f, fmaf(v.z, s_scale[kk + 2], s_shift[kk + 2]));
            v.w = fmaxf(0.f, fmaf(v.w, s_scale[kk + 3], s_shift[kk + 3]));
        }
        As[buf][kq + 0][r] = to_tf32(v.x);
        As[buf][kq + 1][r] = to_tf32(v.y);
        As[buf][kq + 2][r] = to_tf32(v.z);
        As[buf][kq + 3][r] = to_tf32(v.w);
    };
    auto compute = [&](int buf) {
        #pragma unroll
        for (int ks = 0; ks < 2; ks++) {
            const int kb = ks * 8;
            uint32_t afrag[2][4];
            uint32_t bfrag[6][2];
            #pragma unroll
            for (int mt = 0; mt < 2; mt++) {
                int m0 = warp_m * 32 + mt * 16;
                afrag[mt][0] = __float_as_uint(As[buf][kb + q    ][m0 + g    ]);
                afrag[mt][1] = __float_as_uint(As[buf][kb + q    ][m0 + g + 8]);
                afrag[mt][2] = __float_as_uint(As[buf][kb + q + 4][m0 + g    ]);
                afrag[mt][3] = __float_as_uint(As[buf][kb + q + 4][m0 + g + 8]);
            }
            #pragma unroll
            for (int nt = 0; nt < 6; nt++) {
                int n0 = warp_n * 48 + nt * 8;
                bfrag[nt][0] = __float_as_uint(Bs[buf][kb + q    ][n0 + g]);
                bfrag[nt][1] = __float_as_uint(Bs[buf][kb + q + 4][n0 + g]);
            }
            #pragma unroll
            for (int mt = 0; mt < 2; mt++)
                #pragma unroll
                for (int nt = 0; nt < 6; nt++)
                    mma_tf32(acc[mt][nt], afrag[mt], bfrag[nt]);
        }
    };

    // ---- prologue: fill buffer 0 ----
    store_a(0, r_a0, kq_a0, load_a(0, r_a0, kq_a0), kq_a0);
    store_a(0, r_a1, kq_a1, load_a(0, r_a1, kq_a1), kq_a1);
    #pragma unroll
    for (int i = 0; i < 6; i++) {
        int id = tid + i * 256;
        int n = id >> 4, k = id & 15;
        Bs[0][k][n] = to_tf32(W[(size_t)n * KD + k]);
    }
    __syncthreads();

    // ---- steady state: prefetch next, compute current, store next, sync ----
    int cur = 0;
    for (int k0 = BK; k0 < KD; k0 += BK) {
        float4 pa0 = load_a(k0, r_a0, kq_a0);
        float4 pa1 = load_a(k0, r_a1, kq_a1);
        float pb[6];
        #pragma unroll
        for (int i = 0; i < 6; i++) {
            int id = tid + i * 256;
            int n = id >> 4, k = id & 15;
            pb[i] = W[(size_t)n * KD + k0 + k];
        }

        compute(cur);

        store_a(cur ^ 1, r_a0, kq_a0, pa0, k0 + kq_a0);
        store_a(cur ^ 1, r_a1, kq_a1, pa1, k0 + kq_a1);
        #pragma unroll
        for (int i = 0; i < 6; i++) {
            int id = tid + i * 256;
            int n = id >> 4, k = id & 15;
            Bs[cur ^ 1][k][n] = to_tf32(pb[i]);
        }
        __syncthreads();
        cur ^= 1;
    }
    compute(cur);

    // ---- epilogue: bias, store (float2 pairs), fused column reductions ----
    float csum[6][2];
    float csq [6][2];
    #pragma unroll
    for (int nt = 0; nt < 6; nt++)
        #pragma unroll
        for (int j = 0; j < 2; j++) { csum[nt][j] = 0.f; csq[nt][j] = 0.f; }

    #pragma unroll
    for (int nt = 0; nt < 6; nt++) {
        const int col0 = warp_n * 48 + nt * 8 + 2 * q;
        const float2 bb = *(const float2*)(bias + col0);
        #pragma unroll
        for (int mt = 0; mt < 2; mt++) {
            const int grow0 = row0 + warp_m * 32 + mt * 16 + g;
            const int grow1 = grow0 + 8;
            float v0 = acc[mt][nt][0] + bb.x;
            float v1 = acc[mt][nt][1] + bb.y;
            float v2 = acc[mt][nt][2] + bb.x;
            float v3 = acc[mt][nt][3] + bb.y;
            if (grow0 < M) {
                float2 p = make_float2(v0, v1);
                size_t ofs = (size_t)grow0 * H_DIM + col0;
                if (DMODE == 2) *(float2*)(g_h + ofs) = p;
                else            *(float2*)(outp + ofs) = p;
                if (DMODE == 1) *(float2*)(g_z + ofs) = p;
                if (STATS) {
                    csum[nt][0] += v0; csum[nt][1] += v1;
                    if (STATS == 1) { csq[nt][0] += v0 * v0; csq[nt][1] += v1 * v1; }
                }
            }
            if (grow1 < M) {
                float2 p = make_float2(v2, v3);
                size_t ofs = (size_t)grow1 * H_DIM + col0;
                if (DMODE == 2) *(float2*)(g_h + ofs) = p;
                else            *(float2*)(outp + ofs) = p;
                if (DMODE == 1) *(float2*)(g_z + ofs) = p;
                if (STATS) {
                    csum[nt][0] += v2; csum[nt][1] += v3;
                    if (STATS == 1) { csq[nt][0] += v2 * v2; csq[nt][1] += v3 * v3; }
                }
            }
        }
    }
    if (STATS) {
        #pragma unroll
        for (int nt = 0; nt < 6; nt++) {
            #pragma unroll
            for (int j = 0; j < 2; j++) {
                float s = csum[nt][j];
                s += __shfl_xor_sync(0xffffffffu, s, 4);
                s += __shfl_xor_sync(0xffffffffu, s, 8);
                s += __shfl_xor_sync(0xffffffffu, s, 16);
                float qq = 0.f;
                if (STATS == 1) {
                    qq = csq[nt][j];
                    qq += __shfl_xor_sync(0xffffffffu, qq, 4);
                    qq += __shfl_xor_sync(0xffffffffu, qq, 8);
                    qq += __shfl_xor_sync(0xffffffffu, qq, 16);
                }
                if (lane < 4) {
                    int col = warp_n * 48 + nt * 8 + 2 * q + j;
                    if (STATS == 1) {
                        atomicAdd(&g_stats[col], s);
                        atomicAdd(&g_stats[H_DIM + col], qq);
                    } else {
                        atomicAdd(&g_stats[2 * H_DIM + col], s);
                    }
                }
            }
        }
    }
}

// ---------------- edge scatter: g_z[dst] += h0[src], vectorized red.v4 ----------------
__global__ __launch_bounds__(256) void scatter_kernel(const int* __restrict__ ei,
                                                      const float* __restrict__ h0) {
    int gidx = blockIdx.x * 256 + threadIdx.x;   // < E*24 = 19.2M
    int e = gidx / 24;
    int c = (gidx - e * 24) << 2;                // feature offset (0,4,...,92)
    int s = __ldg(ei + e);
    int d = __ldg(ei + E_EDGES + e);
    const float4 v = *(const float4*)(h0 + (size_t)s * H_DIM + c);
    float* p = g_z + (size_t)d * H_DIM + c;
    asm volatile("red.global.add.v4.f32 [%0], {%1, %2, %3, %4};"
                 :: "l"(p), "f"(v.x), "f"(v.y), "f"(v.z), "f"(v.w) : "memory");
}

// ---------------- PairNorm (in place on d_out l1 region) ----------------
__global__ __launch_bounds__(256) void pairnorm_kernel(float* __restrict__ out) {
    int row = blockIdx.x * 8 + (threadIdx.x >> 5);
    if (row >= N_NODES) return;
    int lane = threadIdx.x & 31;
    float* r = out + (size_t)row * H_DIM;
    float v0 = r[lane], v1 = r[lane + 32], v2 = r[lane + 64];
    float ss = v0 * v0 + v1 * v1 + v2 * v2;
    #pragma unroll
    for (int o = 16; o; o >>= 1) ss += __shfl_xor_sync(0xffffffffu, ss, o);
    float sc = PN_SCALE * rsqrtf(1e-6f + ss);
    const float invN = 1.0f / (float)N_NODES;
    r[lane]      = v0 * sc - g_stats[2 * H_DIM + lane]      * invN;
    r[lane + 32] = v1 * sc - g_stats[2 * H_DIM + lane + 32] * invN;
    r[lane + 64] = v2 * sc - g_stats[2 * H_DIM + lane + 64] * invN;
}

// ---------------- launch ----------------
extern "C" void kernel_launch(void* const* d_in, const int* in_sizes, int n_in,
                              void* d_out, int out_size) {
    const float* x     = (const float*)d_in[0];
    const int*   ei    = (const int*)  d_in[1];
    const float* W0    = (const float*)d_in[2];
    const float* b0    = (const float*)d_in[3];
    const float* W1    = (const float*)d_in[4];
    const float* b1    = (const float*)d_in[5];
    const float* gamma = (const float*)d_in[6];
    const float* beta  = (const float*)d_in[7];
    const float* W2    = (const float*)d_in[8];
    const float* b2    = (const float*)d_in[9];

    float* l1 = (float*)d_out;                           // [N, H]
    float* h0 = (float*)d_out + (size_t)N_NODES * H_DIM; // [N, H]

    const int gemm_blocks = (N_NODES + 127) / 128;       // 391

    zero_stats_kernel<<<1, 3 * H_DIM>>>();

    // h0 = x @ W0^T + b0 ; also init g_z = h0
    gemm_kernel<IN_DIM, 0, 1, false, 0><<<gemm_blocks, 256>>>(x, W0, b0, h0, N_NODES);

    // g_z[dst] += h0[src] for all edges (vectorized red)
    scatter_kernel<<<(E_EDGES * 24) / 256, 256>>>(ei, h0);

    // g_h = g_z @ W1^T + b1 ; fused BN sum/sumsq
    gemm_kernel<H_DIM, 1, 2, false, 1><<<gemm_blocks, 256>>>(nullptr, W1, b1, nullptr, N_NODES);

    bn_finalize_kernel<<<1, H_DIM>>>(gamma, beta);

    // l1 = relu(bn(g_h)) @ W2^T + b2 ; fused PairNorm col-sum
    gemm_kernel<H_DIM, 2, 0, true, 2><<<gemm_blocks, 256>>>(nullptr, W2, b2, l1, N_NODES);

    // PairNorm in place
    pairnorm_kernel<<<(N_NODES + 7) / 8, 256>>>(l1);
}

// round 8
// speedup vs baseline: 2.3489x; 1.2802x over previous
#include <cuda_runtime.h>
#include <cuda_bf16.h>
#include <cstdint>
#include <cstddef>

#define N_NODES 50000
#define E_EDGES 800000
#define IN_DIM  128
#define H_DIM   96
#define PN_SCALE 20.0f
#define BN_EPS   1e-5f

// ---------------- scratch (static device globals; no allocation) ----------------
__device__ float g_z[(size_t)N_NODES * H_DIM];      // z = h0 + agg
__device__ float g_h[(size_t)N_NODES * H_DIM];      // h = z@W1^T + b1 (pre-BN)
__device__ float g_stats[3 * H_DIM];                // [0:96) bn sum, [96:192) bn sumsq, [192:288) l1 col sum

// ---------------- helpers ----------------
__device__ __forceinline__ float to_tf32(float x) {
    uint32_t u;
    asm("cvt.rna.tf32.f32 %0, %1;" : "=r"(u) : "f"(x));
    return __uint_as_float(u);
}

__device__ __forceinline__ void mma_tf32(float c[4], const uint32_t a[4], const uint32_t b[2]) {
    asm volatile(
        "mma.sync.aligned.m16n8k8.row.col.f32.tf32.tf32.f32 "
        "{%0,%1,%2,%3},{%4,%5,%6,%7},{%8,%9},{%0,%1,%2,%3};"
        : "+f"(c[0]), "+f"(c[1]), "+f"(c[2]), "+f"(c[3])
        : "r"(a[0]), "r"(a[1]), "r"(a[2]), "r"(a[3]), "r"(b[0]), "r"(b[1]));
}

// ---------------- single-shot full-K tf32 GEMM: out[M,96] = A[M,KD]@W[96,KD]^T + bias --
// Whole 256-row A strip + whole W live in smem; one big batched load phase (high MLP),
// one __syncthreads, then a pure MMA burst. Row-major smem, stride = KD+4 (mod 32 == 4)
// -> all fragment LDS.32 are bank-conflict-free.
//
// AMODE: 0 = A param, 1 = g_z, 2 = g_h
// DMODE: 0 = out param, 1 = out param AND g_z (dual store), 2 = g_h
// TRANS: compute BN affine from g_stats/gamma/beta, apply BN+ReLU to A on smem store
// STATS: 0 none, 1 accumulate BN sum+sumsq of outputs, 2 accumulate col-sum of outputs
//
// Block: 512 thr = 16 warps, 8(M) x 2(N). Tile 256 x 96. Warp tile 32x48 (2x6 m16n8).
template<int KD, int AMODE, int DMODE, bool TRANS, int STATS>
__global__ __launch_bounds__(512, 1) void gemm_kernel(
    const float* __restrict__ A, const float* __restrict__ W,
    const float* __restrict__ bias, const float* __restrict__ gamma,
    const float* __restrict__ beta, float* __restrict__ outp, int M)
{
    constexpr int BM = 256;
    constexpr int STRIDE = KD + 4;          // mod 32 == 4 for KD in {96,128}
    constexpr int F4 = KD / 4;              // float4 per row

    extern __shared__ float smem[];
    float* As      = smem;                   // [BM][STRIDE]
    float* Bs      = As + BM * STRIDE;       // [96][STRIDE]
    float* s_scale = Bs + 96 * STRIDE;       // [96]
    float* s_shift = s_scale + 96;           // [96]
    float* sred    = s_shift + 96;           // [8][96]
    float* sred2   = sred + 8 * 96;          // [8][96]

    const float* Aptr = (AMODE == 0) ? A : ((AMODE == 1) ? g_z : g_h);

    const int tid = threadIdx.x;
    const int lane = tid & 31;
    const int wid = tid >> 5;
    const int warp_n = wid & 1;        // 0..1 -> cols [warp_n*48, +48)
    const int warp_m = wid >> 1;       // 0..7 -> rows [warp_m*32, +32)
    const int g = lane >> 2;           // 0..7
    const int q = lane & 3;            // 0..3
    const int row0 = blockIdx.x * BM;

    // fold zero_stats into gemm0
    if (AMODE == 0 && blockIdx.x == 0 && tid < 3 * H_DIM) g_stats[tid] = 0.0f;

    if (TRANS) {
        if (tid < H_DIM) {
            const float invN = 1.0f / (float)N_NODES;
            float mean = g_stats[tid] * invN;
            float var  = g_stats[H_DIM + tid] * invN - mean * mean;
            float sc = gamma[tid] * rsqrtf(var + BN_EPS);
            s_scale[tid] = sc;
            s_shift[tid] = beta[tid] - mean * sc;
        }
        __syncthreads();
    }

    // ---- batched load phase: whole A strip + whole W, max MLP ----
    #pragma unroll
    for (int i = 0; i < BM * F4 / 512; i++) {
        int id = tid + i * 512;
        int row = id / F4;
        int kq = (id - row * F4) * 4;
        int grow = row0 + row;
        float4 v = make_float4(0.f, 0.f, 0.f, 0.f);
        if (grow < M) v = *(const float4*)(Aptr + (size_t)grow * KD + kq);
        if (TRANS) {
            v.x = fmaxf(0.f, fmaf(v.x, s_scale[kq + 0], s_shift[kq + 0]));
            v.y = fmaxf(0.f, fmaf(v.y, s_scale[kq + 1], s_shift[kq + 1]));
            v.z = fmaxf(0.f, fmaf(v.z, s_scale[kq + 2], s_shift[kq + 2]));
            v.w = fmaxf(0.f, fmaf(v.w, s_scale[kq + 3], s_shift[kq + 3]));
        }
        float4 t = make_float4(to_tf32(v.x), to_tf32(v.y), to_tf32(v.z), to_tf32(v.w));
        *(float4*)&As[row * STRIDE + kq] = t;
    }
    #pragma unroll
    for (int i = 0; i < (96 * F4 + 511) / 512; i++) {
        int id = tid + i * 512;
        if (id < 96 * F4) {
            int n = id / F4;
            int kq = (id - n * F4) * 4;
            float4 v = *(const float4*)(W + (size_t)n * KD + kq);
            float4 t = make_float4(to_tf32(v.x), to_tf32(v.y), to_tf32(v.z), to_tf32(v.w));
            *(float4*)&Bs[n * STRIDE + kq] = t;
        }
    }
    __syncthreads();

    // ---- MMA burst (all from smem, no syncs) ----
    float acc[2][6][4];
    #pragma unroll
    for (int mt = 0; mt < 2; mt++)
        #pragma unroll
        for (int nt = 0; nt < 6; nt++)
            #pragma unroll
            for (int j = 0; j < 4; j++) acc[mt][nt][j] = 0.0f;

    const int m_base0 = warp_m * 32 + g;
    const int n_base  = warp_n * 48 + g;

    #pragma unroll
    for (int kb = 0; kb < KD; kb += 8) {
        uint32_t afrag[2][4];
        uint32_t bfrag[6][2];
        #pragma unroll
        for (int mt = 0; mt < 2; mt++) {
            const float* ap = &As[(m_base0 + mt * 16) * STRIDE + kb + q];
            afrag[mt][0] = __float_as_uint(ap[0]);
            afrag[mt][1] = __float_as_uint(ap[8 * STRIDE]);
            afrag[mt][2] = __float_as_uint(ap[4]);
            afrag[mt][3] = __float_as_uint(ap[8 * STRIDE + 4]);
        }
        #pragma unroll
        for (int nt = 0; nt < 6; nt++) {
            const float* bp = &Bs[(n_base + nt * 8) * STRIDE + kb + q];
            bfrag[nt][0] = __float_as_uint(bp[0]);
            bfrag[nt][1] = __float_as_uint(bp[4]);
        }
        #pragma unroll
        for (int mt = 0; mt < 2; mt++)
            #pragma unroll
            for (int nt = 0; nt < 6; nt++)
                mma_tf32(acc[mt][nt], afrag[mt], bfrag[nt]);
    }

    // ---- epilogue: bias, store, fused column reductions ----
    float2 bb[6];
    #pragma unroll
    for (int nt = 0; nt < 6; nt++)
        bb[nt] = *(const float2*)(bias + warp_n * 48 + nt * 8 + 2 * q);

    float csum[6][2];
    float csq [6][2];
    #pragma unroll
    for (int nt = 0; nt < 6; nt++)
        #pragma unroll
        for (int j = 0; j < 2; j++) { csum[nt][j] = 0.f; csq[nt][j] = 0.f; }

    #pragma unroll
    for (int nt = 0; nt < 6; nt++) {
        const int col0 = warp_n * 48 + nt * 8 + 2 * q;
        #pragma unroll
        for (int mt = 0; mt < 2; mt++) {
            const int grow0 = row0 + warp_m * 32 + mt * 16 + g;
            const int grow1 = grow0 + 8;
            float v0 = acc[mt][nt][0] + bb[nt].x;
            float v1 = acc[mt][nt][1] + bb[nt].y;
            float v2 = acc[mt][nt][2] + bb[nt].x;
            float v3 = acc[mt][nt][3] + bb[nt].y;
            if (grow0 < M) {
                float2 p = make_float2(v0, v1);
                size_t ofs = (size_t)grow0 * H_DIM + col0;
                if (DMODE == 2) *(float2*)(g_h + ofs) = p;
                else            *(float2*)(outp + ofs) = p;
                if (DMODE == 1) *(float2*)(g_z + ofs) = p;
                if (STATS) {
                    csum[nt][0] += v0; csum[nt][1] += v1;
                    if (STATS == 1) { csq[nt][0] += v0 * v0; csq[nt][1] += v1 * v1; }
                }
            }
            if (grow1 < M) {
                float2 p = make_float2(v2, v3);
                size_t ofs = (size_t)grow1 * H_DIM + col0;
                if (DMODE == 2) *(float2*)(g_h + ofs) = p;
                else            *(float2*)(outp + ofs) = p;
                if (DMODE == 1) *(float2*)(g_z + ofs) = p;
                if (STATS) {
                    csum[nt][0] += v2; csum[nt][1] += v3;
                    if (STATS == 1) { csq[nt][0] += v2 * v2; csq[nt][1] += v3 * v3; }
                }
            }
        }
    }

    if (STATS) {
        // warp reduce over rows (lanes with same q), then cross-warp via smem,
        // then ONE global atomicAdd per column per block.
        #pragma unroll
        for (int nt = 0; nt < 6; nt++) {
            #pragma unroll
            for (int j = 0; j < 2; j++) {
                float s = csum[nt][j];
                s += __shfl_xor_sync(0xffffffffu, s, 4);
                s += __shfl_xor_sync(0xffffffffu, s, 8);
                s += __shfl_xor_sync(0xffffffffu, s, 16);
                float qq = 0.f;
                if (STATS == 1) {
                    qq = csq[nt][j];
                    qq += __shfl_xor_sync(0xffffffffu, qq, 4);
                    qq += __shfl_xor_sync(0xffffffffu, qq, 8);
                    qq += __shfl_xor_sync(0xffffffffu, qq, 16);
                }
                if (lane < 4) {
                    int col = warp_n * 48 + nt * 8 + 2 * q + j;
                    sred[warp_m * 96 + col] = s;
                    if (STATS == 1) sred2[warp_m * 96 + col] = qq;
                }
            }
        }
        __syncthreads();
        if (tid < H_DIM) {
            float s = 0.f, qq = 0.f;
            #pragma unroll
            for (int t = 0; t < 8; t++) {
                s += sred[t * 96 + tid];
                if (STATS == 1) qq += sred2[t * 96 + tid];
            }
            if (STATS == 1) {
                atomicAdd(&g_stats[tid], s);
                atomicAdd(&g_stats[H_DIM + tid], qq);
            } else {
                atomicAdd(&g_stats[2 * H_DIM + tid], s);
            }
        }
    }
}

// ---------------- edge scatter: g_z[dst] += h0[src], vectorized red.v4 ----------------
__global__ __launch_bounds__(256) void scatter_kernel(const int* __restrict__ ei,
                                                      const float* __restrict__ h0) {
    int gidx = blockIdx.x * 256 + threadIdx.x;   // < E*24 = 19.2M
    int e = gidx / 24;
    int c = (gidx - e * 24) << 2;                // feature offset (0,4,...,92)
    int s = __ldg(ei + e);
    int d = __ldg(ei + E_EDGES + e);
    const float4 v = *(const float4*)(h0 + (size_t)s * H_DIM + c);
    float* p = g_z + (size_t)d * H_DIM + c;
    asm volatile("red.global.add.v4.f32 [%0], {%1, %2, %3, %4};"
                 :: "l"(p), "f"(v.x), "f"(v.y), "f"(v.z), "f"(v.w) : "memory");
}

// ---------------- PairNorm (in place on d_out l1 region) ----------------
__global__ __launch_bounds__(256) void pairnorm_kernel(float* __restrict__ out) {
    int row = blockIdx.x * 8 + (threadIdx.x >> 5);
    if (row >= N_NODES) return;
    int lane = threadIdx.x & 31;
    float* r = out + (size_t)row * H_DIM;
    float v0 = r[lane], v1 = r[lane + 32], v2 = r[lane + 64];
    float ss = v0 * v0 + v1 * v1 + v2 * v2;
    #pragma unroll
    for (int o = 16; o; o >>= 1) ss += __shfl_xor_sync(0xffffffffu, ss, o);
    float sc = PN_SCALE * rsqrtf(1e-6f + ss);
    const float invN = 1.0f / (float)N_NODES;
    r[lane]      = v0 * sc - g_stats[2 * H_DIM + lane]      * invN;
    r[lane + 32] = v1 * sc - g_stats[2 * H_DIM + lane + 32] * invN;
    r[lane + 64] = v2 * sc - g_stats[2 * H_DIM + lane + 64] * invN;
}

// ---------------- launch ----------------
static inline int gemm_smem_bytes(int KD) {
    int stride = KD + 4;
    return (256 * stride + 96 * stride + 192 + 2 * 8 * 96) * 4;
}

extern "C" void kernel_launch(void* const* d_in, const int* in_sizes, int n_in,
                              void* d_out, int out_size) {
    const float* x     = (const float*)d_in[0];
    const int*   ei    = (const int*)  d_in[1];
    const float* W0    = (const float*)d_in[2];
    const float* b0    = (const float*)d_in[3];
    const float* W1    = (const float*)d_in[4];
    const float* b1    = (const float*)d_in[5];
    const float* W2    = (const float*)d_in[6];  // placeholder; fixed below
    const float* gamma = (const float*)d_in[6];
    const float* beta  = (const float*)d_in[7];
    W2                 = (const float*)d_in[8];
    const float* b2    = (const float*)d_in[9];

    float* l1 = (float*)d_out;                           // [N, H]
    float* h0 = (float*)d_out + (size_t)N_NODES * H_DIM; // [N, H]

    const int gemm_blocks = (N_NODES + 255) / 256;       // 196
    const int smem0 = gemm_smem_bytes(IN_DIM);           // 192768
    const int smemH = gemm_smem_bytes(H_DIM);            // 147712

    // opt-in to large dynamic smem (idempotent host-side calls; not stream ops)
    cudaFuncSetAttribute(gemm_kernel<IN_DIM, 0, 1, false, 0>,
                         cudaFuncAttributeMaxDynamicSharedMemorySize, smem0);
    cudaFuncSetAttribute(gemm_kernel<H_DIM, 1, 2, false, 1>,
                         cudaFuncAttributeMaxDynamicSharedMemorySize, smemH);
    cudaFuncSetAttribute(gemm_kernel<H_DIM, 2, 0, true, 2>,
                         cudaFuncAttributeMaxDynamicSharedMemorySize, smemH);

    // h0 = x @ W0^T + b0 ; also init g_z = h0 ; zeroes g_stats (block 0)
    gemm_kernel<IN_DIM, 0, 1, false, 0><<<gemm_blocks, 512, smem0>>>(
        x, W0, b0, nullptr, nullptr, h0, N_NODES);

    // g_z[dst] += h0[src] for all edges (vectorized red)
    scatter_kernel<<<(E_EDGES * 24) / 256, 256>>>(ei, h0);

    // g_h = g_z @ W1^T + b1 ; fused BN sum/sumsq (one atomic per col per block)
    gemm_kernel<H_DIM, 1, 2, false, 1><<<gemm_blocks, 512, smemH>>>(
        nullptr, W1, b1, nullptr, nullptr, nullptr, N_NODES);

    // l1 = relu(bn(g_h)) @ W2^T + b2 ; BN finalize fused in prologue; PairNorm col-sum fused
    gemm_kernel<H_DIM, 2, 0, true, 2><<<gemm_blocks, 512, smemH>>>(
        nullptr, W2, b2, gamma, beta, l1, N_NODES);

    // PairNorm in place
    pairnorm_kernel<<<(N_NODES + 7) / 8, 256>>>(l1);
}

// round 9
// speedup vs baseline: 2.9352x; 1.2496x over previous
#include <cuda_runtime.h>
#include <cuda_bf16.h>
#include <cstdint>
#include <cstddef>

#define N_NODES 50000
#define E_EDGES 800000
#define IN_DIM  128
#define H_DIM   96
#define PN_SCALE 20.0f
#define BN_EPS   1e-5f

// ---------------- scratch (static device globals; no allocation) ----------------
__device__ float g_z[(size_t)N_NODES * H_DIM];      // z = h0 + agg
__device__ float g_h[(size_t)N_NODES * H_DIM];      // h = z@W1^T + b1 (pre-BN)
__device__ float g_stats[3 * H_DIM];                // bn sum | bn sumsq | l1 col sum
__device__ int   g_cnt[N_NODES];                    // degree counts -> local excl scan
__device__ int   g_start[N_NODES + 1];              // CSR row offsets
__device__ int   g_cursor[N_NODES];                 // fill cursors
__device__ int   g_csr[E_EDGES];                    // src ids grouped by dst
__device__ int   g_bsum[256];                       // scan block sums
__device__ int   g_boff[256];                       // scanned block offsets

// ---------------- helpers ----------------
__device__ __forceinline__ float to_tf32(float x) {
    uint32_t u;
    asm("cvt.rna.tf32.f32 %0, %1;" : "=r"(u) : "f"(x));
    return __uint_as_float(u);
}

__device__ __forceinline__ void mma_tf32(float c[4], const uint32_t a[4], const uint32_t b[2]) {
    asm volatile(
        "mma.sync.aligned.m16n8k8.row.col.f32.tf32.tf32.f32 "
        "{%0,%1,%2,%3},{%4,%5,%6,%7},{%8,%9},{%0,%1,%2,%3};"
        : "+f"(c[0]), "+f"(c[1]), "+f"(c[2]), "+f"(c[3])
        : "r"(a[0]), "r"(a[1]), "r"(a[2]), "r"(a[3]), "r"(b[0]), "r"(b[1]));
}

__device__ __forceinline__ int warp_iscan(int v, int lane) {
    #pragma unroll
    for (int o = 1; o < 32; o <<= 1) {
        int t = __shfl_up_sync(0xffffffffu, v, o);
        if (lane >= o) v += t;
    }
    return v;
}

// ---------------- CSR build kernels ----------------
__global__ void zero_cnt_kernel() {
    int i = blockIdx.x * 256 + threadIdx.x;
    if (i < N_NODES) g_cnt[i] = 0;
}

__global__ void hist_kernel(const int* __restrict__ ei) {
    int e = blockIdx.x * 256 + threadIdx.x;
    if (e < E_EDGES) atomicAdd(&g_cnt[__ldg(ei + E_EDGES + e)], 1);
}

// exclusive scan of in[0..n) in 256-chunks; out = exclusive-in-block scan; bsum[b] = block total
__global__ void scan_local_kernel(const int* __restrict__ in, int* __restrict__ out,
                                  int* __restrict__ bsum, int n) {
    __shared__ int wsum[8];
    int tid = threadIdx.x, lane = tid & 31, w = tid >> 5;
    int i = blockIdx.x * 256 + tid;
    int v = (i < n) ? in[i] : 0;
    int inc = warp_iscan(v, lane);
    if (lane == 31) wsum[w] = inc;
    __syncthreads();
    if (w == 0) {
        int t = (lane < 8) ? wsum[lane] : 0;
        t = warp_iscan(t, lane);
        if (lane < 8) wsum[lane] = t;
    }
    __syncthreads();
    int off = w ? wsum[w - 1] : 0;
    if (i < n) out[i] = off + inc - v;
    if (bsum != nullptr && tid == 255) bsum[blockIdx.x] = wsum[7];
}

__global__ void scan_add_kernel() {
    int i = blockIdx.x * 256 + threadIdx.x;
    if (i < N_NODES) {
        int st = g_cnt[i] + g_boff[i >> 8];
        g_start[i] = st;
        g_cursor[i] = st;
    }
    if (i == 0) g_start[N_NODES] = E_EDGES;
}

__global__ void fill_kernel(const int* __restrict__ ei) {
    int e = blockIdx.x * 256 + threadIdx.x;
    if (e < E_EDGES) {
        int s = __ldg(ei + e);
        int d = __ldg(ei + E_EDGES + e);
        int pos = atomicAdd(&g_cursor[d], 1);
        g_csr[pos] = s;
    }
}

// ---------------- gather-aggregate: g_z[n] = h0[n] + sum_{s in nbrs(n)} h0[s] --------
// one warp per node; lanes 0..23 each own a float4 (96 floats / 4)
__global__ __launch_bounds__(256) void aggregate_kernel(const float* __restrict__ h0) {
    int node = blockIdx.x * 8 + (threadIdx.x >> 5);
    if (node >= N_NODES) return;
    int lane = threadIdx.x & 31;
    int beg = g_start[node], end = g_start[node + 1];
    float4 acc = make_float4(0.f, 0.f, 0.f, 0.f);
    for (int base = beg; base < end; base += 32) {
        int m = min(32, end - base);
        int si = (base + lane < end) ? g_csr[base + lane] : 0;
        for (int it = 0; it < m; it++) {
            int s = __shfl_sync(0xffffffffu, si, it);
            if (lane < 24) {
                float4 v = *(const float4*)(h0 + (size_t)s * H_DIM + (lane << 2));
                acc.x += v.x; acc.y += v.y; acc.z += v.z; acc.w += v.w;
            }
        }
    }
    if (lane < 24) {
        float4 h = *(const float4*)(h0 + (size_t)node * H_DIM + (lane << 2));
        *(float4*)(g_z + (size_t)node * H_DIM + (lane << 2)) =
            make_float4(h.x + acc.x, h.y + acc.y, h.z + acc.z, h.w + acc.w);
    }
}

// ---------------- single-shot full-K tf32 GEMM ----------------------------------------
// out[M,96] = A[M,KD] @ W[96,KD]^T + bias.  Whole BM-row A strip + whole W in smem,
// one batched load phase, one sync, MMA burst. STRIDE = KD+4 -> conflict-free LDS.
// AMODE: 0=A param, 1=g_z, 2=g_h.  DMODE: 0=outp, 2=g_h.
// TRANS: BN affine (from g_stats/gamma/beta) + ReLU on A load.
// STATS: 0 none, 1 BN sum+sumsq of outputs, 2 col-sum of outputs.
template<int KD, int BM, int NT, int MINB, int AMODE, int DMODE, bool TRANS, int STATS>
__global__ __launch_bounds__(NT, MINB) void gemm_kernel(
    const float* __restrict__ A, const float* __restrict__ W,
    const float* __restrict__ bias, const float* __restrict__ gamma,
    const float* __restrict__ beta, float* __restrict__ outp, int M)
{
    constexpr int STRIDE = KD + 4;
    constexpr int F4 = KD / 4;
    constexpr int WARPS_M = NT / 64;      // warps along M (x2 along N)

    extern __shared__ float smem[];
    float* As      = smem;                     // [BM][STRIDE]
    float* Bs      = As + BM * STRIDE;         // [96][STRIDE]
    float* s_scale = Bs + 96 * STRIDE;         // [96]
    float* s_shift = s_scale + 96;             // [96]
    float* sred    = s_shift + 96;             // [WARPS_M][96]
    float* sred2   = sred + WARPS_M * 96;      // [WARPS_M][96]

    const float* Aptr = (AMODE == 0) ? A : ((AMODE == 1) ? g_z : g_h);

    const int tid = threadIdx.x;
    const int lane = tid & 31;
    const int wid = tid >> 5;
    const int warp_n = wid & 1;
    const int warp_m = wid >> 1;          // 0..WARPS_M-1, 32 rows each
    const int g = lane >> 2;
    const int q = lane & 3;
    const int row0 = blockIdx.x * BM;

    if (AMODE == 0 && blockIdx.x == 0 && tid < 3 * H_DIM) g_stats[tid] = 0.0f;

    if (TRANS) {
        if (tid < H_DIM) {
            const float invN = 1.0f / (float)N_NODES;
            float mean = g_stats[tid] * invN;
            float var  = g_stats[H_DIM + tid] * invN - mean * mean;
            float sc = gamma[tid] * rsqrtf(var + BN_EPS);
            s_scale[tid] = sc;
            s_shift[tid] = beta[tid] - mean * sc;
        }
        __syncthreads();
    }

    // ---- batched load phase ----
    #pragma unroll
    for (int i = 0; i < BM * F4 / NT; i++) {
        int id = tid + i * NT;
        int row = id / F4;
        int kq = (id - row * F4) * 4;
        int grow = row0 + row;
        float4 v = make_float4(0.f, 0.f, 0.f, 0.f);
        if (grow < M) v = *(const float4*)(Aptr + (size_t)grow * KD + kq);
        if (TRANS) {
            v.x = fmaxf(0.f, fmaf(v.x, s_scale[kq + 0], s_shift[kq + 0]));
            v.y = fmaxf(0.f, fmaf(v.y, s_scale[kq + 1], s_shift[kq + 1]));
            v.z = fmaxf(0.f, fmaf(v.z, s_scale[kq + 2], s_shift[kq + 2]));
            v.w = fmaxf(0.f, fmaf(v.w, s_scale[kq + 3], s_shift[kq + 3]));
        }
        *(float4*)&As[row * STRIDE + kq] =
            make_float4(to_tf32(v.x), to_tf32(v.y), to_tf32(v.z), to_tf32(v.w));
    }
    #pragma unroll
    for (int i = 0; i < (96 * F4 + NT - 1) / NT; i++) {
        int id = tid + i * NT;
        if (id < 96 * F4) {
            int n = id / F4;
            int kq = (id - n * F4) * 4;
            float4 v = *(const float4*)(W + (size_t)n * KD + kq);
            *(float4*)&Bs[n * STRIDE + kq] =
                make_float4(to_tf32(v.x), to_tf32(v.y), to_tf32(v.z), to_tf32(v.w));
        }
    }
    __syncthreads();

    // ---- MMA burst ----
    float acc[2][6][4];
    #pragma unroll
    for (int mt = 0; mt < 2; mt++)
        #pragma unroll
        for (int nt = 0; nt < 6; nt++)
            #pragma unroll
            for (int j = 0; j < 4; j++) acc[mt][nt][j] = 0.0f;

    const int m_base0 = warp_m * 32 + g;
    const int n_base  = warp_n * 48 + g;

    #pragma unroll
    for (int kb = 0; kb < KD; kb += 8) {
        uint32_t afrag[2][4];
        uint32_t bfrag[6][2];
        #pragma unroll
        for (int mt = 0; mt < 2; mt++) {
            const float* ap = &As[(m_base0 + mt * 16) * STRIDE + kb + q];
            afrag[mt][0] = __float_as_uint(ap[0]);
            afrag[mt][1] = __float_as_uint(ap[8 * STRIDE]);
            afrag[mt][2] = __float_as_uint(ap[4]);
            afrag[mt][3] = __float_as_uint(ap[8 * STRIDE + 4]);
        }
        #pragma unroll
        for (int nt = 0; nt < 6; nt++) {
            const float* bp = &Bs[(n_base + nt * 8) * STRIDE + kb + q];
            bfrag[nt][0] = __float_as_uint(bp[0]);
            bfrag[nt][1] = __float_as_uint(bp[4]);
        }
        #pragma unroll
        for (int mt = 0; mt < 2; mt++)
            #pragma unroll
            for (int nt = 0; nt < 6; nt++)
                mma_tf32(acc[mt][nt], afrag[mt], bfrag[nt]);
    }

    // ---- epilogue ----
    float2 bb[6];
    #pragma unroll
    for (int nt = 0; nt < 6; nt++)
        bb[nt] = *(const float2*)(bias + warp_n * 48 + nt * 8 + 2 * q);

    float csum[6][2];
    float csq [6][2];
    #pragma unroll
    for (int nt = 0; nt < 6; nt++)
        #pragma unroll
        for (int j = 0; j < 2; j++) { csum[nt][j] = 0.f; csq[nt][j] = 0.f; }

    #pragma unroll
    for (int nt = 0; nt < 6; nt++) {
        const int col0 = warp_n * 48 + nt * 8 + 2 * q;
        #pragma unroll
        for (int mt = 0; mt < 2; mt++) {
            const int grow0 = row0 + warp_m * 32 + mt * 16 + g;
            const int grow1 = grow0 + 8;
            float v0 = acc[mt][nt][0] + bb[nt].x;
            float v1 = acc[mt][nt][1] + bb[nt].y;
            float v2 = acc[mt][nt][2] + bb[nt].x;
            float v3 = acc[mt][nt][3] + bb[nt].y;
            if (grow0 < M) {
                float2 p = make_float2(v0, v1);
                size_t ofs = (size_t)grow0 * H_DIM + col0;
                if (DMODE == 2) *(float2*)(g_h + ofs) = p;
                else            *(float2*)(outp + ofs) = p;
                if (STATS) {
                    csum[nt][0] += v0; csum[nt][1] += v1;
                    if (STATS == 1) { csq[nt][0] += v0 * v0; csq[nt][1] += v1 * v1; }
                }
            }
            if (grow1 < M) {
                float2 p = make_float2(v2, v3);
                size_t ofs = (size_t)grow1 * H_DIM + col0;
                if (DMODE == 2) *(float2*)(g_h + ofs) = p;
                else            *(float2*)(outp + ofs) = p;
                if (STATS) {
                    csum[nt][0] += v2; csum[nt][1] += v3;
                    if (STATS == 1) { csq[nt][0] += v2 * v2; csq[nt][1] += v3 * v3; }
                }
            }
        }
    }

    if (STATS) {
        #pragma unroll
        for (int nt = 0; nt < 6; nt++) {
            #pragma unroll
            for (int j = 0; j < 2; j++) {
                float s = csum[nt][j];
                s += __shfl_xor_sync(0xffffffffu, s, 4);
                s += __shfl_xor_sync(0xffffffffu, s, 8);
                s += __shfl_xor_sync(0xffffffffu, s, 16);
                float qq = 0.f;
                if (STATS == 1) {
                    qq = csq[nt][j];
                    qq += __shfl_xor_sync(0xffffffffu, qq, 4);
                    qq += __shfl_xor_sync(0xffffffffu, qq, 8);
                    qq += __shfl_xor_sync(0xffffffffu, qq, 16);
                }
                if (lane < 4) {
                    int col = warp_n * 48 + nt * 8 + 2 * q + j;
                    sred[warp_m * 96 + col] = s;
                    if (STATS == 1) sred2[warp_m * 96 + col] = qq;
                }
            }
        }
        __syncthreads();
        if (tid < H_DIM) {
            float s = 0.f, qq = 0.f;
            #pragma unroll
            for (int t = 0; t < WARPS_M; t++) {
                s += sred[t * 96 + tid];
                if (STATS == 1) qq += sred2[t * 96 + tid];
            }
            if (STATS == 1) {
                atomicAdd(&g_stats[tid], s);
                atomicAdd(&g_stats[H_DIM + tid], qq);
            } else {
                atomicAdd(&g_stats[2 * H_DIM + tid], s);
            }
        }
    }
}

// ---------------- PairNorm (in place on d_out l1 region) ----------------
__global__ __launch_bounds__(256) void pairnorm_kernel(float* __restrict__ out) {
    int row = blockIdx.x * 8 + (threadIdx.x >> 5);
    if (row >= N_NODES) return;
    int lane = threadIdx.x & 31;
    float* r = out + (size_t)row * H_DIM;
    float v0 = r[lane], v1 = r[lane + 32], v2 = r[lane + 64];
    float ss = v0 * v0 + v1 * v1 + v2 * v2;
    #pragma unroll
    for (int o = 16; o; o >>= 1) ss += __shfl_xor_sync(0xffffffffu, ss, o);
    float sc = PN_SCALE * rsqrtf(1e-6f + ss);
    const float invN = 1.0f / (float)N_NODES;
    r[lane]      = v0 * sc - g_stats[2 * H_DIM + lane]      * invN;
    r[lane + 32] = v1 * sc - g_stats[2 * H_DIM + lane + 32] * invN;
    r[lane + 64] = v2 * sc - g_stats[2 * H_DIM + lane + 64] * invN;
}

// ---------------- launch ----------------
static inline int gemm_smem_bytes(int KD, int BM, int NT) {
    int stride = KD + 4;
    int wm = NT / 64;
    return (BM * stride + 96 * stride + 192 + 2 * wm * 96) * 4;
}

extern "C" void kernel_launch(void* const* d_in, const int* in_sizes, int n_in,
                              void* d_out, int out_size) {
    const float* x     = (const float*)d_in[0];
    const int*   ei    = (const int*)  d_in[1];
    const float* W0    = (const float*)d_in[2];
    const float* b0    = (const float*)d_in[3];
    const float* W1    = (const float*)d_in[4];
    const float* b1    = (const float*)d_in[5];
    const float* gamma = (const float*)d_in[6];
    const float* beta  = (const float*)d_in[7];
    const float* W2    = (const float*)d_in[8];
    const float* b2    = (const float*)d_in[9];

    float* l1 = (float*)d_out;                           // [N, H]
    float* h0 = (float*)d_out + (size_t)N_NODES * H_DIM; // [N, H]

    const int smem0 = gemm_smem_bytes(IN_DIM, 256, 512); // 192768
    const int smemH = gemm_smem_bytes(H_DIM, 128, 256);  // 93440

    cudaFuncSetAttribute(gemm_kernel<IN_DIM, 256, 512, 1, 0, 0, false, 0>,
                         cudaFuncAttributeMaxDynamicSharedMemorySize, smem0);
    cudaFuncSetAttribute(gemm_kernel<H_DIM, 128, 256, 2, 1, 2, false, 1>,
                         cudaFuncAttributeMaxDynamicSharedMemorySize, smemH);
    cudaFuncSetAttribute(gemm_kernel<H_DIM, 128, 256, 2, 2, 0, true, 2>,
                         cudaFuncAttributeMaxDynamicSharedMemorySize, smemH);

    const int nb_nodes = (N_NODES + 255) / 256;          // 196
    const int nb_edges = (E_EDGES + 255) / 256;          // 3125

    // ---- CSR build (depends only on edge_index) ----
    zero_cnt_kernel<<<nb_nodes, 256>>>();
    hist_kernel<<<nb_edges, 256>>>(ei);
    {
        int* cnt;  cudaGetSymbolAddress((void**)&cnt,  g_cnt);
        int* bsum; cudaGetSymbolAddress((void**)&bsum, g_bsum);
        int* boff; cudaGetSymbolAddress((void**)&boff, g_boff);
        scan_local_kernel<<<nb_nodes, 256>>>(cnt, cnt, bsum, N_NODES);
        scan_local_kernel<<<1, 256>>>(bsum, boff, nullptr, nb_nodes);
    }
    scan_add_kernel<<<nb_nodes, 256>>>();
    fill_kernel<<<nb_edges, 256>>>(ei);

    // ---- h0 = x @ W0^T + b0 (also zeroes g_stats via block 0) ----
    gemm_kernel<IN_DIM, 256, 512, 1, 0, 0, false, 0><<<196, 512, smem0>>>(
        x, W0, b0, nullptr, nullptr, h0, N_NODES);

    // ---- g_z = h0 + gather-sum over CSR ----
    aggregate_kernel<<<(N_NODES + 7) / 8, 256>>>(h0);

    // ---- g_h = g_z @ W1^T + b1 ; fused BN stats ----
    gemm_kernel<H_DIM, 128, 256, 2, 1, 2, false, 1><<<391, 256, smemH>>>(
        nullptr, W1, b1, nullptr, nullptr, nullptr, N_NODES);

    // ---- l1 = relu(bn(g_h)) @ W2^T + b2 ; BN finalize in prologue; col-sum fused ----
    gemm_kernel<H_DIM, 128, 256, 2, 2, 0, true, 2><<<391, 256, smemH>>>(
        nullptr, W2, b2, gamma, beta, l1, N_NODES);

    // ---- PairNorm in place ----
    pairnorm_kernel<<<(N_NODES + 7) / 8, 256>>>(l1);
}

// round 13
// speedup vs baseline: 3.1901x; 1.0868x over previous
#include <cuda_runtime.h>
#include <cuda_bf16.h>
#include <cstdint>
#include <cstddef>

#define N_NODES 50000
#define E_EDGES 800000
#define IN_DIM  128
#define H_DIM   96
#define PN_SCALE 20.0f
#define BN_EPS   1e-5f

// ---------------- scratch (static device globals; no allocation) ----------------
__device__ float g_z[(size_t)N_NODES * H_DIM];      // z = h0 + agg
__device__ float g_h[(size_t)N_NODES * H_DIM];      // h = z@W1^T + b1 (pre-BN)
__device__ float g_stats[3 * H_DIM];                // bn sum | bn sumsq | l1 col sum
__device__ int   g_cnt[N_NODES];                    // degree counts -> local excl scan (zeroed each pass)
__device__ int   g_start[N_NODES + 1];              // CSR row offsets
__device__ int   g_cursor[N_NODES];                 // fill cursors
__device__ int   g_csr[E_EDGES];                    // src ids grouped by dst
__device__ int   g_bsum[256];                       // scan block sums

// ---------------- helpers ----------------
__device__ __forceinline__ float to_tf32(float x) {
    uint32_t u;
    asm("cvt.rna.tf32.f32 %0, %1;" : "=r"(u) : "f"(x));
    return __uint_as_float(u);
}

__device__ __forceinline__ void mma_tf32(float c[4], const uint32_t a[4], const uint32_t b[2]) {
    asm volatile(
        "mma.sync.aligned.m16n8k8.row.col.f32.tf32.tf32.f32 "
        "{%0,%1,%2,%3},{%4,%5,%6,%7},{%8,%9},{%0,%1,%2,%3};"
        : "+f"(c[0]), "+f"(c[1]), "+f"(c[2]), "+f"(c[3])
        : "r"(a[0]), "r"(a[1]), "r"(a[2]), "r"(a[3]), "r"(b[0]), "r"(b[1]));
}

__device__ __forceinline__ int warp_iscan(int v, int lane) {
    #pragma unroll
    for (int o = 1; o < 32; o <<= 1) {
        int t = __shfl_up_sync(0xffffffffu, v, o);
        if (lane >= o) v += t;
    }
    return v;
}

// ---------------- CSR build kernels ----------------
// hist: 4 edges per thread via int4 load of dst half
__global__ __launch_bounds__(256) void hist_kernel(const int* __restrict__ ei) {
    int i = blockIdx.x * 256 + threadIdx.x;          // quad index
    if (i * 4 < E_EDGES) {
        int4 d = *(const int4*)(ei + E_EDGES + i * 4);
        atomicAdd(&g_cnt[d.x], 1);
        atomicAdd(&g_cnt[d.y], 1);
        atomicAdd(&g_cnt[d.z], 1);
        atomicAdd(&g_cnt[d.w], 1);
    }
}

// exclusive scan of g_cnt in 256-chunks (in place); g_bsum[b] = block total
__global__ void scan_local_kernel() {
    __shared__ int wsum[8];
    int tid = threadIdx.x, lane = tid & 31, w = tid >> 5;
    int i = blockIdx.x * 256 + tid;
    int v = (i < N_NODES) ? g_cnt[i] : 0;
    int inc = warp_iscan(v, lane);
    if (lane == 31) wsum[w] = inc;
    __syncthreads();
    if (w == 0) {
        int t = (lane < 8) ? wsum[lane] : 0;
        t = warp_iscan(t, lane);
        if (lane < 8) wsum[lane] = t;
    }
    __syncthreads();
    int off = w ? wsum[w - 1] : 0;
    if (i < N_NODES) g_cnt[i] = off + inc - v;
    if (tid == 255) g_bsum[blockIdx.x] = wsum[7];
}

// scan_add: block b computes boff = sum(g_bsum[j<b]) itself, writes start/cursor,
// and re-zeroes g_cnt (restores the cnt==0 invariant for the next replay).
__global__ void scan_add_kernel(int nblocks) {
    __shared__ int ws[8];
    int tid = threadIdx.x, lane = tid & 31, w = tid >> 5;
    int b = blockIdx.x;
    int part = 0;
    for (int j = tid; j < b; j += 256) part += g_bsum[j];
    #pragma unroll
    for (int o = 16; o; o >>= 1) part += __shfl_xor_sync(0xffffffffu, part, o);
    if (lane == 0) ws[w] = part;
    __syncthreads();
    int boff = ws[0] + ws[1] + ws[2] + ws[3] + ws[4] + ws[5] + ws[6] + ws[7];

    int i = b * 256 + tid;
    if (i < N_NODES) {
        int st = g_cnt[i] + boff;
        g_start[i] = st;
        g_cursor[i] = st;
        g_cnt[i] = 0;
    }
    if (i == 0) g_start[N_NODES] = E_EDGES;
}

// fill: 4 edges per thread via int4 loads of src and dst halves
__global__ __launch_bounds__(256) void fill_kernel(const int* __restrict__ ei) {
    int i = blockIdx.x * 256 + threadIdx.x;
    if (i * 4 < E_EDGES) {
        int4 s = *(const int4*)(ei + i * 4);
        int4 d = *(const int4*)(ei + E_EDGES + i * 4);
        g_csr[atomicAdd(&g_cursor[d.x], 1)] = s.x;
        g_csr[atomicAdd(&g_cursor[d.y], 1)] = s.y;
        g_csr[atomicAdd(&g_cursor[d.z], 1)] = s.z;
        g_csr[atomicAdd(&g_cursor[d.w], 1)] = s.w;
    }
}

// ---------------- gather-aggregate: g_z[n] = h0[n] + sum_{s in nbrs(n)} h0[s] --------
// one warp per node; lanes 0..23 each own a float4; neighbor loop unrolled x4
__global__ __launch_bounds__(256) void aggregate_kernel(const float* __restrict__ h0) {
    int node = blockIdx.x * 8 + (threadIdx.x >> 5);
    if (node >= N_NODES) return;
    int lane = threadIdx.x & 31;
    int beg = g_start[node], end = g_start[node + 1];
    float4 acc = make_float4(0.f, 0.f, 0.f, 0.f);
    const int c4 = (lane < 24) ? (lane << 2) : 0;
    for (int base = beg; base < end; base += 32) {
        int m = min(32, end - base);
        int si = (base + lane < end) ? g_csr[base + lane] : 0;
        int it = 0;
        for (; it + 4 <= m; it += 4) {
            int s0 = __shfl_sync(0xffffffffu, si, it);
            int s1 = __shfl_sync(0xffffffffu, si, it + 1);
            int s2 = __shfl_sync(0xffffffffu, si, it + 2);
            int s3 = __shfl_sync(0xffffffffu, si, it + 3);
            if (lane < 24) {
                float4 v0 = *(const float4*)(h0 + (size_t)s0 * H_DIM + c4);
                float4 v1 = *(const float4*)(h0 + (size_t)s1 * H_DIM + c4);
                float4 v2 = *(const float4*)(h0 + (size_t)s2 * H_DIM + c4);
                float4 v3 = *(const float4*)(h0 + (size_t)s3 * H_DIM + c4);
                acc.x += (v0.x + v1.x) + (v2.x + v3.x);
                acc.y += (v0.y + v1.y) + (v2.y + v3.y);
                acc.z += (v0.z + v1.z) + (v2.z + v3.z);
                acc.w += (v0.w + v1.w) + (v2.w + v3.w);
            }
        }
        for (; it < m; it++) {
            int s = __shfl_sync(0xffffffffu, si, it);
            if (lane < 24) {
                float4 v = *(const float4*)(h0 + (size_t)s * H_DIM + c4);
                acc.x += v.x; acc.y += v.y; acc.z += v.z; acc.w += v.w;
            }
        }
    }
    if (lane < 24) {
        float4 h = *(const float4*)(h0 + (size_t)node * H_DIM + c4);
        *(float4*)(g_z + (size_t)node * H_DIM + c4) =
            make_float4(h.x + acc.x, h.y + acc.y, h.z + acc.z, h.w + acc.w);
    }
}

// ---------------- single-shot full-K tf32 GEMM ----------------------------------------
// out[M,96] = A[M,KD] @ W[96,KD]^T + bias.  Whole BM-row A strip + whole W in smem,
// one batched load phase, one sync, MMA burst. STRIDE = KD+4 -> conflict-free LDS.
// AMODE: 0=A param, 1=g_z, 2=g_h.  DMODE: 0=outp, 2=g_h.
// TRANS: BN affine (from g_stats/gamma/beta) + ReLU on A load.
// STATS: 0 none, 1 BN sum+sumsq of outputs, 2 col-sum of outputs.
template<int KD, int BM, int NT, int MINB, int AMODE, int DMODE, bool TRANS, int STATS>
__global__ __launch_bounds__(NT, MINB) void gemm_kernel(
    const float* __restrict__ A, const float* __restrict__ W,
    const float* __restrict__ bias, const float* __restrict__ gamma,
    const float* __restrict__ beta, float* __restrict__ outp, int M)
{
    constexpr int STRIDE = KD + 4;
    constexpr int F4 = KD / 4;
    constexpr int WARPS_M = NT / 64;      // warps along M (x2 along N)
    static_assert(BM == WARPS_M * 32, "BM must match warp layout");

    extern __shared__ float smem[];
    float* As      = smem;                     // [BM][STRIDE]
    float* Bs      = As + BM * STRIDE;         // [96][STRIDE]
    float* s_scale = Bs + 96 * STRIDE;         // [96]
    float* s_shift = s_scale + 96;             // [96]
    float* sred    = s_shift + 96;             // [WARPS_M][96]
    float* sred2   = sred + WARPS_M * 96;      // [WARPS_M][96]

    const float* Aptr = (AMODE == 0) ? A : ((AMODE == 1) ? g_z : g_h);

    const int tid = threadIdx.x;
    const int lane = tid & 31;
    const int wid = tid >> 5;
    const int warp_n = wid & 1;
    const int warp_m = wid >> 1;          // 0..WARPS_M-1, 32 rows each
    const int g = lane >> 2;
    const int q = lane & 3;
    const int row0 = blockIdx.x * BM;

    if (AMODE == 0 && blockIdx.x == 0) {
        for (int i = tid; i < 3 * H_DIM; i += NT) g_stats[i] = 0.0f;
    }

    if (TRANS) {
        if (tid < H_DIM) {
            const float invN = 1.0f / (float)N_NODES;
            float mean = g_stats[tid] * invN;
            float var  = g_stats[H_DIM + tid] * invN - mean * mean;
            float sc = gamma[tid] * rsqrtf(var + BN_EPS);
            s_scale[tid] = sc;
            s_shift[tid] = beta[tid] - mean * sc;
        }
        __syncthreads();
    }

    // ---- batched load phase ----
    #pragma unroll
    for (int i = 0; i < BM * F4 / NT; i++) {
        int id = tid + i * NT;
        int row = id / F4;
        int kq = (id - row * F4) * 4;
        int grow = row0 + row;
        float4 v = make_float4(0.f, 0.f, 0.f, 0.f);
        if (grow < M) v = *(const float4*)(Aptr + (size_t)grow * KD + kq);
        if (TRANS) {
            v.x = fmaxf(0.f, fmaf(v.x, s_scale[kq + 0], s_shift[kq + 0]));
            v.y = fmaxf(0.f, fmaf(v.y, s_scale[kq + 1], s_shift[kq + 1]));
            v.z = fmaxf(0.f, fmaf(v.z, s_scale[kq + 2], s_shift[kq + 2]));
            v.w = fmaxf(0.f, fmaf(v.w, s_scale[kq + 3], s_shift[kq + 3]));
        }
        *(float4*)&As[row * STRIDE + kq] =
            make_float4(to_tf32(v.x), to_tf32(v.y), to_tf32(v.z), to_tf32(v.w));
    }
    #pragma unroll
    for (int i = 0; i < (96 * F4 + NT - 1) / NT; i++) {
        int id = tid + i * NT;
        if (id < 96 * F4) {
            int n = id / F4;
            int kq = (id - n * F4) * 4;
            float4 v = *(const float4*)(W + (size_t)n * KD + kq);
            *(float4*)&Bs[n * STRIDE + kq] =
                make_float4(to_tf32(v.x), to_tf32(v.y), to_tf32(v.z), to_tf32(v.w));
        }
    }
    __syncthreads();

    // ---- MMA burst ----
    float acc[2][6][4];
    #pragma unroll
    for (int mt = 0; mt < 2; mt++)
        #pragma unroll
        for (int nt = 0; nt < 6; nt++)
            #pragma unroll
            for (int j = 0; j < 4; j++) acc[mt][nt][j] = 0.0f;

    const int m_base0 = warp_m * 32 + g;
    const int n_base  = warp_n * 48 + g;

    #pragma unroll
    for (int kb = 0; kb < KD; kb += 8) {
        uint32_t afrag[2][4];
        uint32_t bfrag[6][2];
        #pragma unroll
        for (int mt = 0; mt < 2; mt++) {
            const float* ap = &As[(m_base0 + mt * 16) * STRIDE + kb + q];
            afrag[mt][0] = __float_as_uint(ap[0]);
            afrag[mt][1] = __float_as_uint(ap[8 * STRIDE]);
            afrag[mt][2] = __float_as_uint(ap[4]);
            afrag[mt][3] = __float_as_uint(ap[8 * STRIDE + 4]);
        }
        #pragma unroll
        for (int nt = 0; nt < 6; nt++) {
            const float* bp = &Bs[(n_base + nt * 8) * STRIDE + kb + q];
            bfrag[nt][0] = __float_as_uint(bp[0]);
            bfrag[nt][1] = __float_as_uint(bp[4]);
        }
        #pragma unroll
        for (int mt = 0; mt < 2; mt++)
            #pragma unroll
            for (int nt = 0; nt < 6; nt++)
                mma_tf32(acc[mt][nt], afrag[mt], bfrag[nt]);
    }

    // ---- epilogue ----
    float2 bb[6];
    #pragma unroll
    for (int nt = 0; nt < 6; nt++)
        bb[nt] = *(const float2*)(bias + warp_n * 48 + nt * 8 + 2 * q);

    float csum[6][2];
    float csq [6][2];
    #pragma unroll
    for (int nt = 0; nt < 6; nt++)
        #pragma unroll
        for (int j = 0; j < 2; j++) { csum[nt][j] = 0.f; csq[nt][j] = 0.f; }

    #pragma unroll
    for (int nt = 0; nt < 6; nt++) {
        const int col0 = warp_n * 48 + nt * 8 + 2 * q;
        #pragma unroll
        for (int mt = 0; mt < 2; mt++) {
            const int grow0 = row0 + warp_m * 32 + mt * 16 + g;
            const int grow1 = grow0 + 8;
            float v0 = acc[mt][nt][0] + bb[nt].x;
            float v1 = acc[mt][nt][1] + bb[nt].y;
            float v2 = acc[mt][nt][2] + bb[nt].x;
            float v3 = acc[mt][nt][3] + bb[nt].y;
            if (grow0 < M) {
                float2 p = make_float2(v0, v1);
                size_t ofs = (size_t)grow0 * H_DIM + col0;
                if (DMODE == 2) *(float2*)(g_h + ofs) = p;
                else            *(float2*)(outp + ofs) = p;
                if (STATS) {
                    csum[nt][0] += v0; csum[nt][1] += v1;
                    if (STATS == 1) { csq[nt][0] += v0 * v0; csq[nt][1] += v1 * v1; }
                }
            }
            if (grow1 < M) {
                float2 p = make_float2(v2, v3);
                size_t ofs = (size_t)grow1 * H_DIM + col0;
                if (DMODE == 2) *(float2*)(g_h + ofs) = p;
                else            *(float2*)(outp + ofs) = p;
                if (STATS) {
                    csum[nt][0] += v2; csum[nt][1] += v3;
                    if (STATS == 1) { csq[nt][0] += v2 * v2; csq[nt][1] += v3 * v3; }
                }
            }
        }
    }

    if (STATS) {
        #pragma unroll
        for (int nt = 0; nt < 6; nt++) {
            #pragma unroll
            for (int j = 0; j < 2; j++) {
                float s = csum[nt][j];
                s += __shfl_xor_sync(0xffffffffu, s, 4);
                s += __shfl_xor_sync(0xffffffffu, s, 8);
                s += __shfl_xor_sync(0xffffffffu, s, 16);
                float qq = 0.f;
                if (STATS == 1) {
                    qq = csq[nt][j];
                    qq += __shfl_xor_sync(0xffffffffu, qq, 4);
                    qq += __shfl_xor_sync(0xffffffffu, qq, 8);
                    qq += __shfl_xor_sync(0xffffffffu, qq, 16);
                }
                if (lane < 4) {
                    int col = warp_n * 48 + nt * 8 + 2 * q + j;
                    sred[warp_m * 96 + col] = s;
                    if (STATS == 1) sred2[warp_m * 96 + col] = qq;
                }
            }
        }
        __syncthreads();
        if (tid < H_DIM) {
            float s = 0.f, qq = 0.f;
            #pragma unroll
            for (int t = 0; t < WARPS_M; t++) {
                s += sred[t * 96 + tid];
                if (STATS == 1) qq += sred2[t * 96 + tid];
            }
            if (STATS == 1) {
                atomicAdd(&g_stats[tid], s);
                atomicAdd(&g_stats[H_DIM + tid], qq);
            } else {
                atomicAdd(&g_stats[2 * H_DIM + tid], s);
            }
        }
    }
}

// ---------------- PairNorm (in place on d_out l1 region) ----------------
__global__ __launch_bounds__(256) void pairnorm_kernel(float* __restrict__ out) {
    int row = blockIdx.x * 8 + (threadIdx.x >> 5);
    if (row >= N_NODES) return;
    int lane = threadIdx.x & 31;
    float* r = out + (size_t)row * H_DIM;
    float v0 = r[lane], v1 = r[lane + 32], v2 = r[lane + 64];
    float ss = v0 * v0 + v1 * v1 + v2 * v2;
    #pragma unroll
    for (int o = 16; o; o >>= 1) ss += __shfl_xor_sync(0xffffffffu, ss, o);
    float sc = PN_SCALE * rsqrtf(1e-6f + ss);
    const float invN = 1.0f / (float)N_NODES;
    r[lane]      = v0 * sc - g_stats[2 * H_DIM + lane]      * invN;
    r[lane + 32] = v1 * sc - g_stats[2 * H_DIM + lane + 32] * invN;
    r[lane + 64] = v2 * sc - g_stats[2 * H_DIM + lane + 64] * invN;
}

// ---------------- launch ----------------
static inline int gemm_smem_bytes(int KD, int BM, int NT) {
    int stride = KD + 4;
    int wm = NT / 64;
    return (BM * stride + 96 * stride + 192 + 2 * wm * 96) * 4;
}

extern "C" void kernel_launch(void* const* d_in, const int* in_sizes, int n_in,
                              void* d_out, int out_size) {
    const float* x     = (const float*)d_in[0];
    const int*   ei    = (const int*)  d_in[1];
    const float* W0    = (const float*)d_in[2];
    const float* b0    = (const float*)d_in[3];
    const float* W1    = (const float*)d_in[4];
    const float* b1    = (const float*)d_in[5];
    const float* gamma = (const float*)d_in[6];
    const float* beta  = (const float*)d_in[7];
    const float* W2    = (const float*)d_in[8];
    const float* b2    = (const float*)d_in[9];

    float* l1 = (float*)d_out;                           // [N, H]
    float* h0 = (float*)d_out + (size_t)N_NODES * H_DIM; // [N, H]

    const int smem0 = gemm_smem_bytes(IN_DIM, 96, 192);  // 104448
    const int smemH = gemm_smem_bytes(H_DIM, 128, 256);  // 93440

    cudaFuncSetAttribute(gemm_kernel<IN_DIM, 96, 192, 2, 0, 0, false, 0>,
                         cudaFuncAttributeMaxDynamicSharedMemorySize, smem0);
    cudaFuncSetAttribute(gemm_kernel<H_DIM, 128, 256, 2, 1, 2, false, 1>,
                         cudaFuncAttributeMaxDynamicSharedMemorySize, smemH);
    cudaFuncSetAttribute(gemm_kernel<H_DIM, 128, 256, 2, 2, 0, true, 2>,
                         cudaFuncAttributeMaxDynamicSharedMemorySize, smemH);

    const int nb_nodes = (N_NODES + 255) / 256;          // 196
    const int nb_quads = (E_EDGES / 4 + 255) / 256;      // 782

    // ---- CSR build (g_cnt==0 on entry; scan_add re-zeroes it) ----
    hist_kernel<<<nb_quads, 256>>>(ei);
    scan_local_kernel<<<nb_nodes, 256>>>();
    scan_add_kernel<<<nb_nodes, 256>>>(nb_nodes);
    fill_kernel<<<nb_quads, 256>>>(ei);

    // ---- h0 = x @ W0^T + b0 (also zeroes g_stats via block 0); 2 CTAs/SM ----
    gemm_kernel<IN_DIM, 96, 192, 2, 0, 0, false, 0><<<(N_NODES + 95) / 96, 192, smem0>>>(
        x, W0, b0, nullptr, nullptr, h0, N_NODES);

    // ---- g_z = h0 + gather-sum over CSR ----
    aggregate_kernel<<<(N_NODES + 7) / 8, 256>>>(h0);

    // ---- g_h = g_z @ W1^T + b1 ; fused BN stats ----
    gemm_kernel<H_DIM, 128, 256, 2, 1, 2, false, 1><<<(N_NODES + 127) / 128, 256, smemH>>>(
        nullptr, W1, b1, nullptr, nullptr, nullptr, N_NODES);

    // ---- l1 = relu(bn(g_h)) @ W2^T + b2 ; BN finalize in prologue; col-sum fused ----
    gemm_kernel<H_DIM, 128, 256, 2, 2, 0, true, 2><<<(N_NODES + 127) / 128, 256, smemH>>>(
        nullptr, W2, b2, gamma, beta, l1, N_NODES);

    // ---- PairNorm in place ----
    pairnorm_kernel<<<(N_NODES + 7) / 8, 256>>>(l1);
}